// round 12
// baseline (speedup 1.0000x reference)
#include <cuda_runtime.h>
#include <cuda_bf16.h>
#include <cstdint>

#define B_      8
#define C_      512
#define T_      1024
#define HEADS_  8
#define CH_     64
#define S_      77
#define L_      1101
#define LP_     1152
#define GROUPS_ 32
#define CPG_    16

// Scratch (static device globals)
static __device__ __nv_bfloat16 g_nrmb[B_ * C_ * T_];
static __device__ __nv_bfloat16 g_attb[B_ * C_ * T_];
static __device__ __nv_bfloat16 g_qp[B_ * HEADS_ * CH_ * T_];   // [bh][ch][t], pre-scaled 1/8
static __device__ __nv_bfloat16 g_kp[B_ * HEADS_ * CH_ * LP_];  // [bh][ch][self|enc|pad]
static __device__ __nv_bfloat16 g_vp[B_ * HEADS_ * CH_ * LP_];
static __device__ __nv_bfloat16 g_qkvwb[1536 * 512];
static __device__ __nv_bfloat16 g_ekvwb[1024 * 512];
static __device__ __nv_bfloat16 g_projwb[512 * 512];
static __device__ __nv_bfloat16 g_encb[B_ * 512 * 256];         // padded 77->256, zero-filled

// ---------------------------------------------------------------------------
// PTX helpers
// ---------------------------------------------------------------------------
__device__ __forceinline__ uint32_t smem_u32(const void* p) {
    uint32_t a;
    asm("{ .reg .u64 t; cvta.to.shared.u64 t, %1; cvt.u32.u64 %0, t; }" : "=r"(a) : "l"(p));
    return a;
}
__device__ __forceinline__ void mma_bf16(float* c, const uint32_t* a, const uint32_t* b) {
    asm volatile("mma.sync.aligned.m16n8k16.row.col.f32.bf16.bf16.f32 "
        "{%0,%1,%2,%3}, {%4,%5,%6,%7}, {%8,%9}, {%0,%1,%2,%3};"
        : "+f"(c[0]), "+f"(c[1]), "+f"(c[2]), "+f"(c[3])
        : "r"(a[0]), "r"(a[1]), "r"(a[2]), "r"(a[3]), "r"(b[0]), "r"(b[1]));
}
__device__ __forceinline__ void ldsm4(uint32_t* r, uint32_t a) {
    asm volatile("ldmatrix.sync.aligned.m8n8.x4.shared.b16 {%0,%1,%2,%3}, [%4];"
        : "=r"(r[0]), "=r"(r[1]), "=r"(r[2]), "=r"(r[3]) : "r"(a));
}
__device__ __forceinline__ void ldsm4t(uint32_t* r, uint32_t a) {
    asm volatile("ldmatrix.sync.aligned.m8n8.x4.trans.shared.b16 {%0,%1,%2,%3}, [%4];"
        : "=r"(r[0]), "=r"(r[1]), "=r"(r[2]), "=r"(r[3]) : "r"(a));
}
__device__ __forceinline__ void cp16(uint32_t dst, const void* src) {
    asm volatile("cp.async.cg.shared.global [%0], [%1], 16;" :: "r"(dst), "l"(src));
}
#define CP_COMMIT() asm volatile("cp.async.commit_group;" ::: "memory")
#define CP_WAIT2()  asm volatile("cp.async.wait_group 2;" ::: "memory")

__device__ __forceinline__ __nv_bfloat162 pack2(float a, float b) {
    __nv_bfloat162 w;
    w.x = __float2bfloat16_rn(a);
    w.y = __float2bfloat16_rn(b);
    return w;
}
__device__ __forceinline__ uint32_t pku(float lo, float hi) {
    __nv_bfloat162 t = pack2(lo, hi);
    return *reinterpret_cast<uint32_t*>(&t);
}

// ---------------------------------------------------------------------------
// Fused prep: weight/encoder bf16 conversion + GroupNorm32
// ---------------------------------------------------------------------------
#define NQW 786432
#define NEW 524288
#define NPW 262144
#define NEN 1048576          // 8*512*256
#define NCONVB 10240         // (NQW+NEW+NPW+NEN)/256

__global__ __launch_bounds__(256) void prep_kernel(
    const float* __restrict__ x, const float* __restrict__ gamma,
    const float* __restrict__ beta,
    const float* __restrict__ qkvw, const float* __restrict__ ekvw,
    const float* __restrict__ projw, const float* __restrict__ enc)
{
    if (blockIdx.x < NCONVB) {
        int i = blockIdx.x * 256 + threadIdx.x;
        if (i < NQW) g_qkvwb[i] = __float2bfloat16_rn(qkvw[i]);
        else if (i < NQW + NEW) g_ekvwb[i - NQW] = __float2bfloat16_rn(ekvw[i - NQW]);
        else if (i < NQW + NEW + NPW) g_projwb[i - NQW - NEW] = __float2bfloat16_rn(projw[i - NQW - NEW]);
        else {
            int e = i - NQW - NEW - NPW;
            int t = e & 255, row = e >> 8;   // row = b*512 + c
            g_encb[e] = (t < S_) ? __float2bfloat16_rn(enc[row * S_ + t]) : __nv_bfloat16(0.f);
        }
        return;
    }
    int bg = blockIdx.x - NCONVB;
    int b = bg / GROUPS_, g = bg % GROUPS_;
    const float* xp = x + ((size_t)b * C_ + g * CPG_) * T_;
    __nv_bfloat16* op = g_nrmb + ((size_t)b * C_ + g * CPG_) * T_;
    const int N = CPG_ * T_;

    float s = 0.f, q = 0.f;
    for (int i = threadIdx.x; i < N; i += 256) {
        float v = xp[i];
        s += v; q = fmaf(v, v, q);
    }
    __shared__ float rs[256], rq[256];
    rs[threadIdx.x] = s; rq[threadIdx.x] = q;
    __syncthreads();
    for (int o = 128; o > 0; o >>= 1) {
        if (threadIdx.x < o) { rs[threadIdx.x] += rs[threadIdx.x + o]; rq[threadIdx.x] += rq[threadIdx.x + o]; }
        __syncthreads();
    }
    float mean = rs[0] * (1.f / N);
    float var  = rq[0] * (1.f / N) - mean * mean;
    float inv  = rsqrtf(var + 1e-5f);
    for (int i = threadIdx.x; i < N; i += 256) {
        int c = g * CPG_ + (i >> 10);
        op[i] = __float2bfloat16_rn((xp[i] - mean) * inv * gamma[c] + beta[c]);
    }
}

// ---------------------------------------------------------------------------
// Epilogue pack writer (head-major row decode)
// ---------------------------------------------------------------------------
__device__ __forceinline__ void write_pack(int mode, int z, int m, int n, float v0, float v1, int N) {
    int h, type, ch;
    if (mode == 1) {
        h = m / 192;
        int sub = m - h * 192;
        type = sub >> 6; ch = sub & 63;
    } else {
        h = m >> 7;
        type = (m >> 6) & 1; ch = m & 63;
    }
    size_t row = (size_t)(z * 8 + h) * 64 + ch;
    if (mode == 1) {
        if (type == 0) {
            *(__nv_bfloat162*)&g_qp[row * T_ + n] = pack2(v0 * 0.125f, v1 * 0.125f);
        } else {
            __nv_bfloat16* p = (type == 1 ? g_kp : g_vp) + row * LP_ + n;
            *(__nv_bfloat162*)p = pack2(v0, v1);
        }
    } else {
        __nv_bfloat16* p = (type == 0 ? g_kp : g_vp) + row * LP_ + 1024 + n;
        if (n + 1 < N)      *(__nv_bfloat162*)p = pack2(v0, v1);
        else if (n < N)     *p = __float2bfloat16_rn(v0);
    }
}

// ---------------------------------------------------------------------------
// bf16 mma.sync GEMM v2: CTA tile 128x256, 8 warps as 2(M)x4(N), warp tile
// 64x64 (128 fp32 accums/thread -> 1 CTA/SM, MMA:LDSM = 4:1).
// K-step 32; 4-slot cp.async ring (prefetch distance 3).
// smem 96KB: A slots [0..32K) (8KB, 64B rows), B slots [32K..96K) (16KB, 512B rows).
// Fused second problem (ekv) on the extra gridDim.y rows.
// ---------------------------------------------------------------------------
#define GEMM_SMEM 98304

__global__ __launch_bounds__(256, 1) void gemm_bf(
    const __nv_bfloat16* __restrict__ A, const __nv_bfloat16* __restrict__ Bm,
    const float* __restrict__ bias, const float* __restrict__ res,
    float* __restrict__ Cm, int N, int K, int ldb, long long sB,
    int ldc, long long sC, int mode, int ytiles,
    const __nv_bfloat16* __restrict__ A2, const __nv_bfloat16* __restrict__ B2,
    const float* __restrict__ bias2, int N2, int ldb2, long long sB2, int mode2)
{
    extern __shared__ __nv_bfloat16 dsm[];
    const uint32_t sa = smem_u32(dsm), sb = sa + 32768;   // FIX: B region after 4x8KB A slots

    int bm, bn;
    if (A2 && (int)blockIdx.y >= ytiles) {
        A = A2; Bm = B2; bias = bias2; N = N2; ldb = ldb2; sB = sB2; mode = mode2;
        bm = (((int)blockIdx.y - ytiles) * gridDim.x + blockIdx.x) << 7;
        bn = 0;
    } else {
        bm = blockIdx.y << 7; bn = blockIdx.x << 8;
    }

    int tid = threadIdx.x, wid = tid >> 5, lane = tid & 31;
    int wm = (wid >> 2) << 6;          // 0 or 64
    int wn = (wid & 3) << 6;           // 0,64,128,192
    int gr = lane >> 2, gc = lane & 3;

    const __nv_bfloat16* Ab = A + (size_t)bm * K;
    const __nv_bfloat16* Bb = Bm + (size_t)blockIdx.z * sB + bn;

    int a_m  = (lane & 7) + (((lane >> 3) & 1) << 3);
    int a_kc = lane >> 4;
    int b_kr = (lane & 7) + (((lane >> 3) & 1) << 3);
    int b_sg = ((wid & 3) << 3) + (lane >> 4);   // warp's first seg + lane half

    float c[4][8][4];
#pragma unroll
    for (int i = 0; i < 4; i++)
#pragma unroll
        for (int j = 0; j < 8; j++)
#pragma unroll
            for (int l = 0; l < 4; l++) c[i][j][l] = 0.f;

    // one K-step = 32 k: A 128x32 (8KB, 2 cp16/thr), B 32x256 (16KB, 4 cp16/thr)
    auto load_tiles = [&](int k0, int slot) {
#pragma unroll
        for (int j = 0; j < 2; j++) {
            int idx = tid + (j << 8);
            int m = idx >> 2, kc = idx & 3;
            cp16(sa + slot * 8192 + m * 64 + ((kc ^ ((m >> 1) & 3)) << 4),
                 Ab + (size_t)m * K + k0 + kc * 8);
        }
#pragma unroll
        for (int j = 0; j < 4; j++) {
            int idx = tid + (j << 8);
            int k = idx >> 5, seg = idx & 31;
            cp16(sb + slot * 16384 + k * 512 + ((seg ^ (k & 7)) << 4),
                 Bb + (size_t)(k0 + k) * ldb + seg * 8);
        }
    };

    int nsteps = K >> 5;   // K=512 -> 16
    load_tiles(0, 0); CP_COMMIT();
    load_tiles(32, 1); CP_COMMIT();
    load_tiles(64, 2); CP_COMMIT();

    for (int s = 0; s < nsteps; s++) {
        CP_WAIT2();
        __syncthreads();
        if (s + 3 < nsteps) load_tiles((s + 3) << 5, (s + 3) & 3);
        CP_COMMIT();
        uint32_t ab = sa + (s & 3) * 8192, bb = sb + (s & 3) * 16384;

#pragma unroll
        for (int kt = 0; kt < 2; kt++) {
            uint32_t af[4][4];
            int kc = (kt << 1) + a_kc;
#pragma unroll
            for (int mt = 0; mt < 4; mt++) {
                int m = wm + (mt << 4) + a_m;
                ldsm4(af[mt], ab + m * 64 + ((kc ^ ((m >> 1) & 3)) << 4));
            }
            uint32_t bf[8][2];
            int kr = (kt << 4) + b_kr;
#pragma unroll
            for (int np = 0; np < 4; np++) {
                uint32_t t4[4];
                int seg = b_sg + (np << 1);
                ldsm4t(t4, bb + kr * 512 + ((seg ^ (kr & 7)) << 4));
                bf[np * 2][0] = t4[0]; bf[np * 2][1] = t4[1];
                bf[np * 2 + 1][0] = t4[2]; bf[np * 2 + 1][1] = t4[3];
            }
#pragma unroll
            for (int mt = 0; mt < 4; mt++)
#pragma unroll
                for (int nf = 0; nf < 8; nf++)
                    mma_bf16(c[mt][nf], af[mt], bf[nf]);
        }
    }

    float* Cp = Cm ? (Cm + (size_t)blockIdx.z * sC) : nullptr;
    const float* Rp = res ? (res + (size_t)blockIdx.z * sC) : nullptr;

#pragma unroll
    for (int mt = 0; mt < 4; mt++) {
        int m0 = bm + wm + (mt << 4) + gr;
        float bv0 = bias[m0], bv1 = bias[m0 + 8];
#pragma unroll
        for (int nf = 0; nf < 8; nf++) {
            int n = bn + wn + (nf << 3) + (gc << 1);
            float v0 = c[mt][nf][0] + bv0, v1 = c[mt][nf][1] + bv0;
            float v2 = c[mt][nf][2] + bv1, v3 = c[mt][nf][3] + bv1;
            if (mode == 0) {
                if (Rp) {
                    float2 r0 = *(const float2*)&Rp[(size_t)m0 * ldc + n];
                    float2 r1 = *(const float2*)&Rp[(size_t)(m0 + 8) * ldc + n];
                    v0 += r0.x; v1 += r0.y; v2 += r1.x; v3 += r1.y;
                }
                *(float2*)&Cp[(size_t)m0 * ldc + n]       = make_float2(v0, v1);
                *(float2*)&Cp[(size_t)(m0 + 8) * ldc + n] = make_float2(v2, v3);
            } else {
                write_pack(mode, blockIdx.z, m0, n, v0, v1, N);
                write_pack(mode, blockIdx.z, m0 + 8, n, v2, v3, N);
            }
        }
    }
}

// ---------------------------------------------------------------------------
// bf16 flash attention (unchanged, passing since round 10): P in registers,
// 6-slot cp.async ring consumed in chunk pairs, mask LDS only for encoder cols.
// ---------------------------------------------------------------------------
#define QS_OFF   0
#define KS_OFF   16384
#define VS_OFF   65536
#define MADD_OFF 114688
#define ATT_SMEM 115200

__device__ __forceinline__ void prefetch_kv(uint32_t sbase,
    const __nv_bfloat16* Kg, const __nv_bfloat16* Vg, int c, int slot, int tid)
{
#pragma unroll
    for (int j = 0; j < 4; j++) {
        int i = tid + (j << 8);
        int sel = i >> 9, ch = (i >> 3) & 63, seg = i & 7;
        const __nv_bfloat16* src = (sel ? Vg : Kg) + ch * LP_ + (c << 6) + (seg << 3);
        uint32_t dst = sbase + (sel ? VS_OFF : KS_OFF) + slot * 8192
                     + (ch << 7) + ((seg ^ (ch & 7)) << 4);
        cp16(dst, src);
    }
}

__global__ __launch_bounds__(256, 2) void attn_bf16_kernel(const unsigned int* __restrict__ mask)
{
    extern __shared__ char smc[];
    const uint32_t sbase = smem_u32(smc);
    int tid = threadIdx.x, lane = tid & 31, wid = tid >> 5;
    int gr = lane >> 2, gc = lane & 3, l7 = lane & 7, g = lane >> 3;
    int bh = blockIdx.y, h = bh & 7;
    int t0 = blockIdx.x << 7;
    int r0w = wid << 4;

    const __nv_bfloat16* Qg = g_qp + (size_t)bh * 64 * T_;
    const __nv_bfloat16* Kg = g_kp + (size_t)bh * 64 * LP_;
    const __nv_bfloat16* Vg = g_vp + (size_t)bh * 64 * LP_;

    float* madd = (float*)(smc + MADD_OFF);
    for (int s = tid; s < 128; s += 256) {
        int col = 1024 + s;
        madd[s] = (col < L_) ? (mask[h * S_ + s] ? 0.f : -10000.f) : -1e30f;
    }

    for (int i = tid; i < 1024; i += 256) {
        int ch = i >> 4, seg = i & 15;
        uint4 v = *(const uint4*)(Qg + ch * T_ + t0 + seg * 8);
        *(uint4*)(smc + QS_OFF + ch * 256 + ((seg ^ (ch & 7)) << 4)) = v;
    }
    __syncthreads();

    uint32_t qf[4][4];
#pragma unroll
    for (int kt = 0; kt < 4; kt++) {
        int ch = kt * 16 + l7 + ((g >> 1) << 3);
        int tb = (r0w << 1) + ((g & 1) << 4);
        ldsm4t(qf[kt], sbase + QS_OFF + ch * 256 + (tb ^ ((ch & 7) << 4)));
    }

    float o[8][4];
#pragma unroll
    for (int nt = 0; nt < 8; nt++)
#pragma unroll
        for (int l = 0; l < 4; l++) o[nt][l] = 0.f;
    float lsum0 = 0.f, lsum1 = 0.f;

    auto process = [&](int c, uint32_t kb, uint32_t vb) {
        float s8[8][4];
#pragma unroll
        for (int nt = 0; nt < 8; nt++)
#pragma unroll
            for (int l = 0; l < 4; l++) s8[nt][l] = 0.f;
#pragma unroll
        for (int kt = 0; kt < 4; kt++) {
            int ch = kt * 16 + l7 + ((g & 1) << 3);
#pragma unroll
            for (int ntp = 0; ntp < 4; ntp++) {
                uint32_t bf4[4];
                int seg = ntp * 2 + (g >> 1);
                ldsm4t(bf4, kb + (ch << 7) + ((seg ^ (ch & 7)) << 4));
                mma_bf16(s8[ntp * 2],     qf[kt], bf4);
                mma_bf16(s8[ntp * 2 + 1], qf[kt], bf4 + 2);
            }
        }
        if (c < 16) {
#pragma unroll
            for (int nt = 0; nt < 8; nt++) {
                float p0 = __expf(s8[nt][0]), p1 = __expf(s8[nt][1]);
                float p2 = __expf(s8[nt][2]), p3 = __expf(s8[nt][3]);
                lsum0 += p0 + p1; lsum1 += p2 + p3;
                s8[nt][0] = p0; s8[nt][1] = p1; s8[nt][2] = p2; s8[nt][3] = p3;
            }
        } else {
            int colb = ((c - 16) << 6);
#pragma unroll
            for (int nt = 0; nt < 8; nt++) {
                int col = colb + nt * 8 + gc * 2;
                float m0 = madd[col], m1 = madd[col + 1];
                float p0 = __expf(s8[nt][0] + m0), p1 = __expf(s8[nt][1] + m1);
                float p2 = __expf(s8[nt][2] + m0), p3 = __expf(s8[nt][3] + m1);
                lsum0 += p0 + p1; lsum1 += p2 + p3;
                s8[nt][0] = p0; s8[nt][1] = p1; s8[nt][2] = p2; s8[nt][3] = p3;
            }
        }
#pragma unroll
        for (int kt = 0; kt < 4; kt++) {
            uint32_t af[4];
            af[0] = pku(s8[2 * kt][0],     s8[2 * kt][1]);
            af[1] = pku(s8[2 * kt][2],     s8[2 * kt][3]);
            af[2] = pku(s8[2 * kt + 1][0], s8[2 * kt + 1][1]);
            af[3] = pku(s8[2 * kt + 1][2], s8[2 * kt + 1][3]);
#pragma unroll
            for (int ntp = 0; ntp < 4; ntp++) {
                uint32_t bv4[4];
                int ch = (ntp * 2 + (g >> 1)) * 8 + l7;
                int sseg = kt * 2 + (g & 1);
                ldsm4(bv4, vb + (ch << 7) + ((sseg ^ (ch & 7)) << 4));
                mma_bf16(o[ntp * 2],     af, bv4);
                mma_bf16(o[ntp * 2 + 1], af, bv4 + 2);
            }
        }
    };

    prefetch_kv(sbase, Kg, Vg, 0, 0, tid); CP_COMMIT();
    prefetch_kv(sbase, Kg, Vg, 1, 1, tid); CP_COMMIT();
    prefetch_kv(sbase, Kg, Vg, 2, 2, tid); CP_COMMIT();
    prefetch_kv(sbase, Kg, Vg, 3, 3, tid); CP_COMMIT();

    for (int it = 0; it < 9; it++) {
        int c0 = it << 1;
        CP_WAIT2();
        __syncthreads();
        if (c0 + 4 < 18) prefetch_kv(sbase, Kg, Vg, c0 + 4, (c0 + 4) % 6, tid);
        CP_COMMIT();
        if (c0 + 5 < 18) prefetch_kv(sbase, Kg, Vg, c0 + 5, (c0 + 5) % 6, tid);
        CP_COMMIT();
        int s0 = c0 % 6, s1 = (c0 + 1) % 6;
        process(c0,     sbase + KS_OFF + s0 * 8192, sbase + VS_OFF + s0 * 8192);
        process(c0 + 1, sbase + KS_OFF + s1 * 8192, sbase + VS_OFF + s1 * 8192);
    }

    lsum0 += __shfl_xor_sync(0xffffffffu, lsum0, 1);
    lsum0 += __shfl_xor_sync(0xffffffffu, lsum0, 2);
    lsum1 += __shfl_xor_sync(0xffffffffu, lsum1, 1);
    lsum1 += __shfl_xor_sync(0xffffffffu, lsum1, 2);
    float inv0 = 1.f / lsum0, inv1 = 1.f / lsum1;

    __syncthreads();
    float* tr = (float*)smc;   // [64][132] floats
    int r0g = r0w + gr;
#pragma unroll
    for (int nt = 0; nt < 8; nt++) {
        int ch = nt * 8 + gc * 2;
        tr[ch * 132 + r0g]           = o[nt][0] * inv0;
        tr[(ch + 1) * 132 + r0g]     = o[nt][1] * inv0;
        tr[ch * 132 + r0g + 8]       = o[nt][2] * inv1;
        tr[(ch + 1) * 132 + r0g + 8] = o[nt][3] * inv1;
    }
    __syncthreads();
    __nv_bfloat16* ob = g_attb + ((size_t)(bh >> 3) * C_ + h * CH_) * T_ + t0;
    for (int i = tid; i < 8192; i += 256) {
        int ch = i >> 7, t = i & 127;
        ob[(size_t)ch * T_ + t] = __float2bfloat16_rn(tr[ch * 132 + t]);
    }
}

// ---------------------------------------------------------------------------
extern "C" void kernel_launch(void* const* d_in, const int* in_sizes, int n_in,
                              void* d_out, int out_size)
{
    (void)in_sizes; (void)n_in; (void)out_size;
    const float* x       = (const float*)d_in[0];
    const float* enc     = (const float*)d_in[1];
    const unsigned int* mask = (const unsigned int*)d_in[2];
    const float* gamma   = (const float*)d_in[3];
    const float* beta    = (const float*)d_in[4];
    const float* qkv_w   = (const float*)d_in[5];
    const float* qkv_b   = (const float*)d_in[6];
    const float* ekv_w   = (const float*)d_in[7];
    const float* ekv_b   = (const float*)d_in[8];
    const float* proj_w  = (const float*)d_in[9];
    const float* proj_b  = (const float*)d_in[10];
    float* out = (float*)d_out;

    __nv_bfloat16 *qkvwb, *ekvwb, *projwb, *encb, *nrmb, *attb;
    cudaGetSymbolAddress((void**)&qkvwb, g_qkvwb);
    cudaGetSymbolAddress((void**)&ekvwb, g_ekvwb);
    cudaGetSymbolAddress((void**)&projwb, g_projwb);
    cudaGetSymbolAddress((void**)&encb, g_encb);
    cudaGetSymbolAddress((void**)&nrmb, g_nrmb);
    cudaGetSymbolAddress((void**)&attb, g_attb);

    cudaFuncSetAttribute(gemm_bf, cudaFuncAttributeMaxDynamicSharedMemorySize, GEMM_SMEM);
    cudaFuncSetAttribute(attn_bf16_kernel, cudaFuncAttributeMaxDynamicSharedMemorySize, ATT_SMEM);

    // 1. fused weight/encoder conversion + GroupNorm
    prep_kernel<<<NCONVB + B_ * GROUPS_, 256>>>(x, gamma, beta, qkv_w, ekv_w, proj_w, enc);

    // 2. fused qkv (12 y-rows, 4 n-tiles of 256) + ekv (2 extra y-rows = 8 m-tiles)
    gemm_bf<<<dim3(4, 14, B_), 256, GEMM_SMEM>>>(qkvwb, nrmb, qkv_b, nullptr, nullptr,
        1024, 512, T_, (long long)C_ * T_, 0, 0, 1, 12,
        ekvwb, encb, ekv_b, S_, 256, (long long)512 * 256, 2);

    // 3. bf16 flash attention
    attn_bf16_kernel<<<dim3(8, 64), 256, ATT_SMEM>>>(mask);

    // 4. output projection + bias + residual -> d_out
    gemm_bf<<<dim3(4, 4, B_), 256, GEMM_SMEM>>>(projwb, attb, proj_b, x, out,
        1024, 512, T_, (long long)C_ * T_, T_, (long long)C_ * T_, 0, 4,
        nullptr, nullptr, nullptr, 0, 0, 0, 0);
}

// round 13
// speedup vs baseline: 1.0847x; 1.0847x over previous
#include <cuda_runtime.h>
#include <cuda_fp16.h>
#include <cstdint>

#define B_      8
#define C_      512
#define T_      1024
#define HEADS_  8
#define CH_     64
#define S_      77
#define L_      1101
#define LP_     1152
#define GROUPS_ 32
#define CPG_    16

// Scratch (static device globals) — all 16-bit tensors are fp16
static __device__ __half g_nrmb[B_ * C_ * T_];
static __device__ __half g_attb[B_ * C_ * T_];
static __device__ __half g_qp[B_ * HEADS_ * CH_ * T_];   // [bh][ch][t], pre-scaled 1/8
static __device__ __half g_kp[B_ * HEADS_ * CH_ * LP_];  // [bh][ch][self|enc|pad]
static __device__ __half g_vp[B_ * HEADS_ * CH_ * LP_];
static __device__ __half g_qkvwb[1536 * 512];
static __device__ __half g_ekvwb[1024 * 512];
static __device__ __half g_projwb[512 * 512];
static __device__ __half g_encb[B_ * 512 * 256];         // padded 77->256, zero-filled

// ---------------------------------------------------------------------------
// PTX helpers
// ---------------------------------------------------------------------------
__device__ __forceinline__ uint32_t smem_u32(const void* p) {
    uint32_t a;
    asm("{ .reg .u64 t; cvta.to.shared.u64 t, %1; cvt.u32.u64 %0, t; }" : "=r"(a) : "l"(p));
    return a;
}
// f16 inputs, f32 accum (attention)
__device__ __forceinline__ void mma_hf32(float* c, const uint32_t* a, const uint32_t* b) {
    asm volatile("mma.sync.aligned.m16n8k16.row.col.f32.f16.f16.f32 "
        "{%0,%1,%2,%3}, {%4,%5,%6,%7}, {%8,%9}, {%0,%1,%2,%3};"
        : "+f"(c[0]), "+f"(c[1]), "+f"(c[2]), "+f"(c[3])
        : "r"(a[0]), "r"(a[1]), "r"(a[2]), "r"(a[3]), "r"(b[0]), "r"(b[1]));
}
// f16 inputs, f16 accum (GEMM): D/C are 2 x f16x2 regs
__device__ __forceinline__ void mma_hf16(uint32_t* c, const uint32_t* a, const uint32_t* b) {
    asm volatile("mma.sync.aligned.m16n8k16.row.col.f16.f16.f16.f16 "
        "{%0,%1}, {%2,%3,%4,%5}, {%6,%7}, {%0,%1};"
        : "+r"(c[0]), "+r"(c[1])
        : "r"(a[0]), "r"(a[1]), "r"(a[2]), "r"(a[3]), "r"(b[0]), "r"(b[1]));
}
__device__ __forceinline__ void ldsm4(uint32_t* r, uint32_t a) {
    asm volatile("ldmatrix.sync.aligned.m8n8.x4.shared.b16 {%0,%1,%2,%3}, [%4];"
        : "=r"(r[0]), "=r"(r[1]), "=r"(r[2]), "=r"(r[3]) : "r"(a));
}
__device__ __forceinline__ void ldsm4t(uint32_t* r, uint32_t a) {
    asm volatile("ldmatrix.sync.aligned.m8n8.x4.trans.shared.b16 {%0,%1,%2,%3}, [%4];"
        : "=r"(r[0]), "=r"(r[1]), "=r"(r[2]), "=r"(r[3]) : "r"(a));
}
__device__ __forceinline__ void cp16(uint32_t dst, const void* src) {
    asm volatile("cp.async.cg.shared.global [%0], [%1], 16;" :: "r"(dst), "l"(src));
}
#define CP_COMMIT() asm volatile("cp.async.commit_group;" ::: "memory")
#define CP_WAIT1()  asm volatile("cp.async.wait_group 1;" ::: "memory")
#define CP_WAIT2()  asm volatile("cp.async.wait_group 2;" ::: "memory")

__device__ __forceinline__ __half2 pack2h(float a, float b) {
    return __floats2half2_rn(a, b);
}
__device__ __forceinline__ uint32_t pku(float lo, float hi) {
    __half2 t = __floats2half2_rn(lo, hi);
    return *reinterpret_cast<uint32_t*>(&t);
}

// ---------------------------------------------------------------------------
// Fused prep: weight/encoder fp16 conversion + GroupNorm32
// ---------------------------------------------------------------------------
#define NQW 786432
#define NEW 524288
#define NPW 262144
#define NEN 1048576          // 8*512*256
#define NCONVB 10240

__global__ __launch_bounds__(256) void prep_kernel(
    const float* __restrict__ x, const float* __restrict__ gamma,
    const float* __restrict__ beta,
    const float* __restrict__ qkvw, const float* __restrict__ ekvw,
    const float* __restrict__ projw, const float* __restrict__ enc)
{
    if (blockIdx.x < NCONVB) {
        int i = blockIdx.x * 256 + threadIdx.x;
        if (i < NQW) g_qkvwb[i] = __float2half_rn(qkvw[i]);
        else if (i < NQW + NEW) g_ekvwb[i - NQW] = __float2half_rn(ekvw[i - NQW]);
        else if (i < NQW + NEW + NPW) g_projwb[i - NQW - NEW] = __float2half_rn(projw[i - NQW - NEW]);
        else {
            int e = i - NQW - NEW - NPW;
            int t = e & 255, row = e >> 8;
            g_encb[e] = (t < S_) ? __float2half_rn(enc[row * S_ + t]) : __half(0.f);
        }
        return;
    }
    int bg = blockIdx.x - NCONVB;
    int b = bg / GROUPS_, g = bg % GROUPS_;
    const float* xp = x + ((size_t)b * C_ + g * CPG_) * T_;
    __half* op = g_nrmb + ((size_t)b * C_ + g * CPG_) * T_;
    const int N = CPG_ * T_;

    float s = 0.f, q = 0.f;
    for (int i = threadIdx.x; i < N; i += 256) {
        float v = xp[i];
        s += v; q = fmaf(v, v, q);
    }
    __shared__ float rs[256], rq[256];
    rs[threadIdx.x] = s; rq[threadIdx.x] = q;
    __syncthreads();
    for (int o = 128; o > 0; o >>= 1) {
        if (threadIdx.x < o) { rs[threadIdx.x] += rs[threadIdx.x + o]; rq[threadIdx.x] += rq[threadIdx.x + o]; }
        __syncthreads();
    }
    float mean = rs[0] * (1.f / N);
    float var  = rq[0] * (1.f / N) - mean * mean;
    float inv  = rsqrtf(var + 1e-5f);
    for (int i = threadIdx.x; i < N; i += 256) {
        int c = g * CPG_ + (i >> 10);
        op[i] = __float2half_rn((xp[i] - mean) * inv * gamma[c] + beta[c]);
    }
}

// ---------------------------------------------------------------------------
// Epilogue pack writer (head-major row decode)
// ---------------------------------------------------------------------------
__device__ __forceinline__ void write_pack(int mode, int z, int m, int n, float v0, float v1, int N) {
    int h, type, ch;
    if (mode == 1) {
        h = m / 192;
        int sub = m - h * 192;
        type = sub >> 6; ch = sub & 63;
    } else {
        h = m >> 7;
        type = (m >> 6) & 1; ch = m & 63;
    }
    size_t row = (size_t)(z * 8 + h) * 64 + ch;
    if (mode == 1) {
        if (type == 0) {
            *(__half2*)&g_qp[row * T_ + n] = pack2h(v0 * 0.125f, v1 * 0.125f);
        } else {
            __half* p = (type == 1 ? g_kp : g_vp) + row * LP_ + n;
            *(__half2*)p = pack2h(v0, v1);
        }
    } else {
        __half* p = (type == 0 ? g_kp : g_vp) + row * LP_ + 1024 + n;
        if (n + 1 < N)      *(__half2*)p = pack2h(v0, v1);
        else if (n < N)     *p = __float2half_rn(v0);
    }
}

// ---------------------------------------------------------------------------
// fp16 mma.sync GEMM v3: CTA tile 128x256, 8 warps 2(M)x4(N), warp tile 64x64
// with f16 ACCUMULATORS (64 regs) -> ~115 regs total -> 2 CTAs/SM, MMA:LDSM 4:1.
// K-step 32; 4-slot cp.async ring (distance 3).
// smem 96KB: A slots [0..32K) (8KB, 64B rows), B slots [32K..96K) (16KB, 512B rows).
// Fused second problem (ekv) on the extra gridDim.y rows.
// ---------------------------------------------------------------------------
#define GEMM_SMEM 98304

__global__ __launch_bounds__(256, 2) void gemm_hf(
    const __half* __restrict__ A, const __half* __restrict__ Bm,
    const float* __restrict__ bias, const float* __restrict__ res,
    float* __restrict__ Cm, int N, int K, int ldb, long long sB,
    int ldc, long long sC, int mode, int ytiles,
    const __half* __restrict__ A2, const __half* __restrict__ B2,
    const float* __restrict__ bias2, int N2, int ldb2, long long sB2, int mode2)
{
    extern __shared__ __half dsm[];
    const uint32_t sa = smem_u32(dsm), sb = sa + 32768;

    int bm, bn;
    if (A2 && (int)blockIdx.y >= ytiles) {
        A = A2; Bm = B2; bias = bias2; N = N2; ldb = ldb2; sB = sB2; mode = mode2;
        bm = (((int)blockIdx.y - ytiles) * gridDim.x + blockIdx.x) << 7;
        bn = 0;
    } else {
        bm = blockIdx.y << 7; bn = blockIdx.x << 8;
    }

    int tid = threadIdx.x, wid = tid >> 5, lane = tid & 31;
    int wm = (wid >> 2) << 6;          // 0 or 64
    int wn = (wid & 3) << 6;           // 0,64,128,192
    int gr = lane >> 2, gc = lane & 3;

    const __half* Ab = A + (size_t)bm * K;
    const __half* Bb = Bm + (size_t)blockIdx.z * sB + bn;

    int a_m  = (lane & 7) + (((lane >> 3) & 1) << 3);
    int a_kc = lane >> 4;
    int b_kr = (lane & 7) + (((lane >> 3) & 1) << 3);
    int b_sg = ((wid & 3) << 3) + (lane >> 4);

    uint32_t c[4][8][2];   // f16x2 accumulators
#pragma unroll
    for (int i = 0; i < 4; i++)
#pragma unroll
        for (int j = 0; j < 8; j++) { c[i][j][0] = 0u; c[i][j][1] = 0u; }

    auto load_tiles = [&](int k0, int slot) {
#pragma unroll
        for (int j = 0; j < 2; j++) {
            int idx = tid + (j << 8);
            int m = idx >> 2, kc = idx & 3;
            cp16(sa + slot * 8192 + m * 64 + ((kc ^ ((m >> 1) & 3)) << 4),
                 Ab + (size_t)m * K + k0 + kc * 8);
        }
#pragma unroll
        for (int j = 0; j < 4; j++) {
            int idx = tid + (j << 8);
            int k = idx >> 5, seg = idx & 31;
            cp16(sb + slot * 16384 + k * 512 + ((seg ^ (k & 7)) << 4),
                 Bb + (size_t)(k0 + k) * ldb + seg * 8);
        }
    };

    int nsteps = K >> 5;   // 16
    load_tiles(0, 0); CP_COMMIT();
    load_tiles(32, 1); CP_COMMIT();
    load_tiles(64, 2); CP_COMMIT();

    for (int s = 0; s < nsteps; s++) {
        CP_WAIT2();
        __syncthreads();
        if (s + 3 < nsteps) load_tiles((s + 3) << 5, (s + 3) & 3);
        CP_COMMIT();
        uint32_t ab = sa + (s & 3) * 8192, bb = sb + (s & 3) * 16384;

#pragma unroll
        for (int kt = 0; kt < 2; kt++) {
            uint32_t af[4][4];
            int kc = (kt << 1) + a_kc;
#pragma unroll
            for (int mt = 0; mt < 4; mt++) {
                int m = wm + (mt << 4) + a_m;
                ldsm4(af[mt], ab + m * 64 + ((kc ^ ((m >> 1) & 3)) << 4));
            }
            int kr = (kt << 4) + b_kr;
#pragma unroll
            for (int np = 0; np < 4; np++) {
                uint32_t t4[4];
                int seg = b_sg + (np << 1);
                ldsm4t(t4, bb + kr * 512 + ((seg ^ (kr & 7)) << 4));
#pragma unroll
                for (int mt = 0; mt < 4; mt++) {
                    mma_hf16(c[mt][np * 2],     af[mt], t4);
                    mma_hf16(c[mt][np * 2 + 1], af[mt], t4 + 2);
                }
            }
        }
    }

    float* Cp = Cm ? (Cm + (size_t)blockIdx.z * sC) : nullptr;
    const float* Rp = res ? (res + (size_t)blockIdx.z * sC) : nullptr;

#pragma unroll
    for (int mt = 0; mt < 4; mt++) {
        int m0 = bm + wm + (mt << 4) + gr;
        float bv0 = bias[m0], bv1 = bias[m0 + 8];
#pragma unroll
        for (int nf = 0; nf < 8; nf++) {
            int n = bn + wn + (nf << 3) + (gc << 1);
            float2 lo = __half22float2(*(__half2*)&c[mt][nf][0]);
            float2 hi = __half22float2(*(__half2*)&c[mt][nf][1]);
            float v0 = lo.x + bv0, v1 = lo.y + bv0;
            float v2 = hi.x + bv1, v3 = hi.y + bv1;
            if (mode == 0) {
                if (Rp) {
                    float2 r0 = *(const float2*)&Rp[(size_t)m0 * ldc + n];
                    float2 r1 = *(const float2*)&Rp[(size_t)(m0 + 8) * ldc + n];
                    v0 += r0.x; v1 += r0.y; v2 += r1.x; v3 += r1.y;
                }
                *(float2*)&Cp[(size_t)m0 * ldc + n]       = make_float2(v0, v1);
                *(float2*)&Cp[(size_t)(m0 + 8) * ldc + n] = make_float2(v2, v3);
            } else {
                write_pack(mode, blockIdx.z, m0, n, v0, v1, N);
                write_pack(mode, blockIdx.z, m0 + 8, n, v2, v3, N);
            }
        }
    }
}

// ---------------------------------------------------------------------------
// fp16 flash attention (round-10 structure, f32 accum): P in registers,
// 6-slot cp.async ring consumed in chunk pairs, mask LDS only for encoder cols.
// ---------------------------------------------------------------------------
#define QS_OFF   0
#define KS_OFF   16384
#define VS_OFF   65536
#define MADD_OFF 114688
#define ATT_SMEM 115200

__device__ __forceinline__ void prefetch_kv(uint32_t sbase,
    const __half* Kg, const __half* Vg, int c, int slot, int tid)
{
#pragma unroll
    for (int j = 0; j < 4; j++) {
        int i = tid + (j << 8);
        int sel = i >> 9, ch = (i >> 3) & 63, seg = i & 7;
        const __half* src = (sel ? Vg : Kg) + ch * LP_ + (c << 6) + (seg << 3);
        uint32_t dst = sbase + (sel ? VS_OFF : KS_OFF) + slot * 8192
                     + (ch << 7) + ((seg ^ (ch & 7)) << 4);
        cp16(dst, src);
    }
}

__global__ __launch_bounds__(256, 2) void attn_hf_kernel(const unsigned int* __restrict__ mask)
{
    extern __shared__ char smc[];
    const uint32_t sbase = smem_u32(smc);
    int tid = threadIdx.x, lane = tid & 31, wid = tid >> 5;
    int gr = lane >> 2, gc = lane & 3, l7 = lane & 7, g = lane >> 3;
    int bh = blockIdx.y, h = bh & 7;
    int t0 = blockIdx.x << 7;
    int r0w = wid << 4;

    const __half* Qg = g_qp + (size_t)bh * 64 * T_;
    const __half* Kg = g_kp + (size_t)bh * 64 * LP_;
    const __half* Vg = g_vp + (size_t)bh * 64 * LP_;

    float* madd = (float*)(smc + MADD_OFF);
    for (int s = tid; s < 128; s += 256) {
        int col = 1024 + s;
        madd[s] = (col < L_) ? (mask[h * S_ + s] ? 0.f : -10000.f) : -1e30f;
    }

    for (int i = tid; i < 1024; i += 256) {
        int ch = i >> 4, seg = i & 15;
        uint4 v = *(const uint4*)(Qg + ch * T_ + t0 + seg * 8);
        *(uint4*)(smc + QS_OFF + ch * 256 + ((seg ^ (ch & 7)) << 4)) = v;
    }
    __syncthreads();

    uint32_t qf[4][4];
#pragma unroll
    for (int kt = 0; kt < 4; kt++) {
        int ch = kt * 16 + l7 + ((g >> 1) << 3);
        int tb = (r0w << 1) + ((g & 1) << 4);
        ldsm4t(qf[kt], sbase + QS_OFF + ch * 256 + (tb ^ ((ch & 7) << 4)));
    }

    float o[8][4];
#pragma unroll
    for (int nt = 0; nt < 8; nt++)
#pragma unroll
        for (int l = 0; l < 4; l++) o[nt][l] = 0.f;
    float lsum0 = 0.f, lsum1 = 0.f;

    auto process = [&](int c, uint32_t kb, uint32_t vb) {
        float s8[8][4];
#pragma unroll
        for (int nt = 0; nt < 8; nt++)
#pragma unroll
            for (int l = 0; l < 4; l++) s8[nt][l] = 0.f;
#pragma unroll
        for (int kt = 0; kt < 4; kt++) {
            int ch = kt * 16 + l7 + ((g & 1) << 3);
#pragma unroll
            for (int ntp = 0; ntp < 4; ntp++) {
                uint32_t bf4[4];
                int seg = ntp * 2 + (g >> 1);
                ldsm4t(bf4, kb + (ch << 7) + ((seg ^ (ch & 7)) << 4));
                mma_hf32(s8[ntp * 2],     qf[kt], bf4);
                mma_hf32(s8[ntp * 2 + 1], qf[kt], bf4 + 2);
            }
        }
        if (c < 16) {
#pragma unroll
            for (int nt = 0; nt < 8; nt++) {
                float p0 = __expf(s8[nt][0]), p1 = __expf(s8[nt][1]);
                float p2 = __expf(s8[nt][2]), p3 = __expf(s8[nt][3]);
                lsum0 += p0 + p1; lsum1 += p2 + p3;
                s8[nt][0] = p0; s8[nt][1] = p1; s8[nt][2] = p2; s8[nt][3] = p3;
            }
        } else {
            int colb = ((c - 16) << 6);
#pragma unroll
            for (int nt = 0; nt < 8; nt++) {
                int col = colb + nt * 8 + gc * 2;
                float m0 = madd[col], m1 = madd[col + 1];
                float p0 = __expf(s8[nt][0] + m0), p1 = __expf(s8[nt][1] + m1);
                float p2 = __expf(s8[nt][2] + m0), p3 = __expf(s8[nt][3] + m1);
                lsum0 += p0 + p1; lsum1 += p2 + p3;
                s8[nt][0] = p0; s8[nt][1] = p1; s8[nt][2] = p2; s8[nt][3] = p3;
            }
        }
#pragma unroll
        for (int kt = 0; kt < 4; kt++) {
            uint32_t af[4];
            af[0] = pku(s8[2 * kt][0],     s8[2 * kt][1]);
            af[1] = pku(s8[2 * kt][2],     s8[2 * kt][3]);
            af[2] = pku(s8[2 * kt + 1][0], s8[2 * kt + 1][1]);
            af[3] = pku(s8[2 * kt + 1][2], s8[2 * kt + 1][3]);
#pragma unroll
            for (int ntp = 0; ntp < 4; ntp++) {
                uint32_t bv4[4];
                int ch = (ntp * 2 + (g >> 1)) * 8 + l7;
                int sseg = kt * 2 + (g & 1);
                ldsm4(bv4, vb + (ch << 7) + ((sseg ^ (ch & 7)) << 4));
                mma_hf32(o[ntp * 2],     af, bv4);
                mma_hf32(o[ntp * 2 + 1], af, bv4 + 2);
            }
        }
    };

    prefetch_kv(sbase, Kg, Vg, 0, 0, tid); CP_COMMIT();
    prefetch_kv(sbase, Kg, Vg, 1, 1, tid); CP_COMMIT();
    prefetch_kv(sbase, Kg, Vg, 2, 2, tid); CP_COMMIT();
    prefetch_kv(sbase, Kg, Vg, 3, 3, tid); CP_COMMIT();

    for (int it = 0; it < 9; it++) {
        int c0 = it << 1;
        CP_WAIT2();
        __syncthreads();
        if (c0 + 4 < 18) prefetch_kv(sbase, Kg, Vg, c0 + 4, (c0 + 4) % 6, tid);
        CP_COMMIT();
        if (c0 + 5 < 18) prefetch_kv(sbase, Kg, Vg, c0 + 5, (c0 + 5) % 6, tid);
        CP_COMMIT();
        int s0 = c0 % 6, s1 = (c0 + 1) % 6;
        process(c0,     sbase + KS_OFF + s0 * 8192, sbase + VS_OFF + s0 * 8192);
        process(c0 + 1, sbase + KS_OFF + s1 * 8192, sbase + VS_OFF + s1 * 8192);
    }

    lsum0 += __shfl_xor_sync(0xffffffffu, lsum0, 1);
    lsum0 += __shfl_xor_sync(0xffffffffu, lsum0, 2);
    lsum1 += __shfl_xor_sync(0xffffffffu, lsum1, 1);
    lsum1 += __shfl_xor_sync(0xffffffffu, lsum1, 2);
    float inv0 = 1.f / lsum0, inv1 = 1.f / lsum1;

    __syncthreads();
    float* tr = (float*)smc;   // [64][132] floats
    int r0g = r0w + gr;
#pragma unroll
    for (int nt = 0; nt < 8; nt++) {
        int ch = nt * 8 + gc * 2;
        tr[ch * 132 + r0g]           = o[nt][0] * inv0;
        tr[(ch + 1) * 132 + r0g]     = o[nt][1] * inv0;
        tr[ch * 132 + r0g + 8]       = o[nt][2] * inv1;
        tr[(ch + 1) * 132 + r0g + 8] = o[nt][3] * inv1;
    }
    __syncthreads();
    __half* ob = g_attb + ((size_t)(bh >> 3) * C_ + h * CH_) * T_ + t0;
    for (int i = tid; i < 8192; i += 256) {
        int ch = i >> 7, t = i & 127;
        ob[(size_t)ch * T_ + t] = __float2half_rn(tr[ch * 132 + t]);
    }
}

// ---------------------------------------------------------------------------
extern "C" void kernel_launch(void* const* d_in, const int* in_sizes, int n_in,
                              void* d_out, int out_size)
{
    (void)in_sizes; (void)n_in; (void)out_size;
    const float* x       = (const float*)d_in[0];
    const float* enc     = (const float*)d_in[1];
    const unsigned int* mask = (const unsigned int*)d_in[2];
    const float* gamma   = (const float*)d_in[3];
    const float* beta    = (const float*)d_in[4];
    const float* qkv_w   = (const float*)d_in[5];
    const float* qkv_b   = (const float*)d_in[6];
    const float* ekv_w   = (const float*)d_in[7];
    const float* ekv_b   = (const float*)d_in[8];
    const float* proj_w  = (const float*)d_in[9];
    const float* proj_b  = (const float*)d_in[10];
    float* out = (float*)d_out;

    __half *qkvwb, *ekvwb, *projwb, *encb, *nrmb, *attb;
    cudaGetSymbolAddress((void**)&qkvwb, g_qkvwb);
    cudaGetSymbolAddress((void**)&ekvwb, g_ekvwb);
    cudaGetSymbolAddress((void**)&projwb, g_projwb);
    cudaGetSymbolAddress((void**)&encb, g_encb);
    cudaGetSymbolAddress((void**)&nrmb, g_nrmb);
    cudaGetSymbolAddress((void**)&attb, g_attb);

    cudaFuncSetAttribute(gemm_hf, cudaFuncAttributeMaxDynamicSharedMemorySize, GEMM_SMEM);
    cudaFuncSetAttribute(attn_hf_kernel, cudaFuncAttributeMaxDynamicSharedMemorySize, ATT_SMEM);

    // 1. fused weight/encoder conversion + GroupNorm
    prep_kernel<<<NCONVB + B_ * GROUPS_, 256>>>(x, gamma, beta, qkv_w, ekv_w, proj_w, enc);

    // 2. fused qkv (12 y-rows, 4 n-tiles of 256) + ekv (2 extra y-rows = 8 m-tiles)
    gemm_hf<<<dim3(4, 14, B_), 256, GEMM_SMEM>>>(qkvwb, nrmb, qkv_b, nullptr, nullptr,
        1024, 512, T_, (long long)C_ * T_, 0, 0, 1, 12,
        ekvwb, encb, ekv_b, S_, 256, (long long)512 * 256, 2);

    // 3. fp16 flash attention
    attn_hf_kernel<<<dim3(8, 64), 256, ATT_SMEM>>>(mask);

    // 4. output projection + bias + residual -> d_out
    gemm_hf<<<dim3(4, 4, B_), 256, GEMM_SMEM>>>(projwb, attb, proj_b, x, out,
        1024, 512, T_, (long long)C_ * T_, T_, (long long)C_ * T_, 0, 4,
        nullptr, nullptr, nullptr, 0, 0, 0, 0);
}

// round 14
// speedup vs baseline: 1.1810x; 1.0887x over previous
#include <cuda_runtime.h>
#include <cuda_fp16.h>
#include <cstdint>

#define B_      8
#define C_      512
#define T_      1024
#define HEADS_  8
#define CH_     64
#define S_      77
#define L_      1101
#define LP_     1152
#define GROUPS_ 32
#define CPG_    16

// Scratch (static device globals) — all 16-bit tensors are fp16
static __device__ __half g_nrmb[B_ * C_ * T_];
static __device__ __half g_attb[B_ * C_ * T_];
static __device__ __half g_qp[B_ * HEADS_ * CH_ * T_];   // [bh][ch][t], pre-scaled 1/8
static __device__ __half g_kp[B_ * HEADS_ * CH_ * LP_];  // [bh][ch][self|enc|pad]
static __device__ __half g_vp[B_ * HEADS_ * CH_ * LP_];
static __device__ __half g_qkvwb[1536 * 512];
static __device__ __half g_ekvwb[1024 * 512];
static __device__ __half g_projwb[512 * 512];
static __device__ __half g_encb[B_ * 512 * 256];         // padded 77->256, zero-filled

// ---------------------------------------------------------------------------
// PTX helpers
// ---------------------------------------------------------------------------
__device__ __forceinline__ uint32_t smem_u32(const void* p) {
    uint32_t a;
    asm("{ .reg .u64 t; cvta.to.shared.u64 t, %1; cvt.u32.u64 %0, t; }" : "=r"(a) : "l"(p));
    return a;
}
__device__ __forceinline__ void mma_hf32(float* c, const uint32_t* a, const uint32_t* b) {
    asm volatile("mma.sync.aligned.m16n8k16.row.col.f32.f16.f16.f32 "
        "{%0,%1,%2,%3}, {%4,%5,%6,%7}, {%8,%9}, {%0,%1,%2,%3};"
        : "+f"(c[0]), "+f"(c[1]), "+f"(c[2]), "+f"(c[3])
        : "r"(a[0]), "r"(a[1]), "r"(a[2]), "r"(a[3]), "r"(b[0]), "r"(b[1]));
}
__device__ __forceinline__ void ldsm4(uint32_t* r, uint32_t a) {
    asm volatile("ldmatrix.sync.aligned.m8n8.x4.shared.b16 {%0,%1,%2,%3}, [%4];"
        : "=r"(r[0]), "=r"(r[1]), "=r"(r[2]), "=r"(r[3]) : "r"(a));
}
__device__ __forceinline__ void ldsm4t(uint32_t* r, uint32_t a) {
    asm volatile("ldmatrix.sync.aligned.m8n8.x4.trans.shared.b16 {%0,%1,%2,%3}, [%4];"
        : "=r"(r[0]), "=r"(r[1]), "=r"(r[2]), "=r"(r[3]) : "r"(a));
}
__device__ __forceinline__ void cp16(uint32_t dst, const void* src) {
    asm volatile("cp.async.cg.shared.global [%0], [%1], 16;" :: "r"(dst), "l"(src));
}
#define CP_COMMIT() asm volatile("cp.async.commit_group;" ::: "memory")
#define CP_WAIT2()  asm volatile("cp.async.wait_group 2;" ::: "memory")

__device__ __forceinline__ __half2 pack2h(float a, float b) {
    return __floats2half2_rn(a, b);
}
__device__ __forceinline__ uint32_t pku(float lo, float hi) {
    __half2 t = __floats2half2_rn(lo, hi);
    return *reinterpret_cast<uint32_t*>(&t);
}

// ---------------------------------------------------------------------------
// Fused prep: weight/encoder fp16 conversion + GroupNorm32
// ---------------------------------------------------------------------------
#define NQW 786432
#define NEW 524288
#define NPW 262144
#define NEN 1048576
#define NCONVB 10240

__global__ __launch_bounds__(256) void prep_kernel(
    const float* __restrict__ x, const float* __restrict__ gamma,
    const float* __restrict__ beta,
    const float* __restrict__ qkvw, const float* __restrict__ ekvw,
    const float* __restrict__ projw, const float* __restrict__ enc)
{
    if (blockIdx.x < NCONVB) {
        int i = blockIdx.x * 256 + threadIdx.x;
        if (i < NQW) g_qkvwb[i] = __float2half_rn(qkvw[i]);
        else if (i < NQW + NEW) g_ekvwb[i - NQW] = __float2half_rn(ekvw[i - NQW]);
        else if (i < NQW + NEW + NPW) g_projwb[i - NQW - NEW] = __float2half_rn(projw[i - NQW - NEW]);
        else {
            int e = i - NQW - NEW - NPW;
            int t = e & 255, row = e >> 8;
            g_encb[e] = (t < S_) ? __float2half_rn(enc[row * S_ + t]) : __half(0.f);
        }
        return;
    }
    int bg = blockIdx.x - NCONVB;
    int b = bg / GROUPS_, g = bg % GROUPS_;
    const float* xp = x + ((size_t)b * C_ + g * CPG_) * T_;
    __half* op = g_nrmb + ((size_t)b * C_ + g * CPG_) * T_;
    const int N = CPG_ * T_;

    float s = 0.f, q = 0.f;
    for (int i = threadIdx.x; i < N; i += 256) {
        float v = xp[i];
        s += v; q = fmaf(v, v, q);
    }
    __shared__ float rs[256], rq[256];
    rs[threadIdx.x] = s; rq[threadIdx.x] = q;
    __syncthreads();
    for (int o = 128; o > 0; o >>= 1) {
        if (threadIdx.x < o) { rs[threadIdx.x] += rs[threadIdx.x + o]; rq[threadIdx.x] += rq[threadIdx.x + o]; }
        __syncthreads();
    }
    float mean = rs[0] * (1.f / N);
    float var  = rq[0] * (1.f / N) - mean * mean;
    float inv  = rsqrtf(var + 1e-5f);
    for (int i = threadIdx.x; i < N; i += 256) {
        int c = g * CPG_ + (i >> 10);
        op[i] = __float2half_rn((xp[i] - mean) * inv * gamma[c] + beta[c]);
    }
}

// ---------------------------------------------------------------------------
// Epilogue pack writer (head-major row decode)
// ---------------------------------------------------------------------------
__device__ __forceinline__ void write_pack(int mode, int z, int m, int n, float v0, float v1, int N) {
    int h, type, ch;
    if (mode == 1) {
        h = m / 192;
        int sub = m - h * 192;
        type = sub >> 6; ch = sub & 63;
    } else {
        h = m >> 7;
        type = (m >> 6) & 1; ch = m & 63;
    }
    size_t row = (size_t)(z * 8 + h) * 64 + ch;
    if (mode == 1) {
        if (type == 0) {
            *(__half2*)&g_qp[row * T_ + n] = pack2h(v0 * 0.125f, v1 * 0.125f);
        } else {
            __half* p = (type == 1 ? g_kp : g_vp) + row * LP_ + n;
            *(__half2*)p = pack2h(v0, v1);
        }
    } else {
        __half* p = (type == 0 ? g_kp : g_vp) + row * LP_ + 1024 + n;
        if (n + 1 < N)      *(__half2*)p = pack2h(v0, v1);
        else if (n < N)     *p = __float2half_rn(v0);
    }
}

// ---------------------------------------------------------------------------
// fp16 mma.sync GEMM v4: CTA tile 128(M)x64(N), 128 threads / 4 warps, each
// warp 32(M)x64(N), f32 accums. K-step 32, 4-slot cp.async ring (distance 3).
// smem 48KB/CTA -> 4 CTAs/SM. A: 64B rows, kc^((m>>1)&3); B: 128B rows,
// seg^(k&7) (identical to attention K-tile pattern).
// Fused second problem (ekv) on the extra gridDim.y row.
// ---------------------------------------------------------------------------
#define GEMM_SMEM 49152

__global__ __launch_bounds__(128, 4) void gemm_hf(
    const __half* __restrict__ A, const __half* __restrict__ Bm,
    const float* __restrict__ bias, const float* __restrict__ res,
    float* __restrict__ Cm, int N, int K, int ldb, long long sB,
    int ldc, long long sC, int mode, int ytiles,
    const __half* __restrict__ A2, const __half* __restrict__ B2,
    const float* __restrict__ bias2, int N2, int ldb2, long long sB2, int mode2)
{
    extern __shared__ __half dsm[];
    const uint32_t sa = smem_u32(dsm), sb = sa + 32768;   // A 4x8KB, B 4x4KB

    int bm, bn;
    if (A2 && (int)blockIdx.y >= ytiles) {
        // ekv: M=1024 (8 m-tiles), N=77 (2 n-tiles of 64); blockIdx.x in [0,16)
        A = A2; Bm = B2; bias = bias2; N = N2; ldb = ldb2; sB = sB2; mode = mode2;
        bm = ((int)blockIdx.x >> 1) << 7;
        bn = ((int)blockIdx.x & 1) << 6;
    } else {
        bm = blockIdx.y << 7; bn = blockIdx.x << 6;
    }

    int tid = threadIdx.x, wid = tid >> 5, lane = tid & 31;
    int wm = wid << 5;                 // warp owns rows [wm, wm+32)
    int gr = lane >> 2, gc = lane & 3;
    int l7 = lane & 7, g = lane >> 3;

    const __half* Ab = A + (size_t)bm * K;
    const __half* Bb = Bm + (size_t)blockIdx.z * sB + bn;

    int a_m  = l7 + ((g & 1) << 3);    // row offset within m16
    int a_kc = lane >> 4;              // 0/1

    float c[2][8][4];
#pragma unroll
    for (int i = 0; i < 2; i++)
#pragma unroll
        for (int j = 0; j < 8; j++)
#pragma unroll
            for (int l = 0; l < 4; l++) c[i][j][l] = 0.f;

    // one K-step = 32 k: A 128x32 (8KB, 4 cp16/thr), B 32x64 (4KB, 2 cp16/thr)
    auto load_tiles = [&](int k0, int slot) {
#pragma unroll
        for (int j = 0; j < 4; j++) {
            int idx = tid + (j << 7);
            int m = idx >> 2, kc = idx & 3;
            cp16(sa + slot * 8192 + m * 64 + ((kc ^ ((m >> 1) & 3)) << 4),
                 Ab + (size_t)m * K + k0 + kc * 8);
        }
#pragma unroll
        for (int j = 0; j < 2; j++) {
            int idx = tid + (j << 7);
            int k = idx >> 3, seg = idx & 7;
            cp16(sb + slot * 4096 + k * 128 + ((seg ^ (k & 7)) << 4),
                 Bb + (size_t)(k0 + k) * ldb + seg * 8);
        }
    };

    int nsteps = K >> 5;   // 16
    load_tiles(0, 0); CP_COMMIT();
    load_tiles(32, 1); CP_COMMIT();
    load_tiles(64, 2); CP_COMMIT();

    for (int s = 0; s < nsteps; s++) {
        CP_WAIT2();
        __syncthreads();
        if (s + 3 < nsteps) load_tiles((s + 3) << 5, (s + 3) & 3);
        CP_COMMIT();
        uint32_t ab = sa + (s & 3) * 8192, bb = sb + (s & 3) * 4096;

#pragma unroll
        for (int kt = 0; kt < 2; kt++) {
            // A fragments: 2 m16 tiles for this warp
            uint32_t af[2][4];
            int kc = (kt << 1) + a_kc;
#pragma unroll
            for (int mt = 0; mt < 2; mt++) {
                int m = wm + (mt << 4) + a_m;
                ldsm4(af[mt], ab + m * 64 + ((kc ^ ((m >> 1) & 3)) << 4));
            }
            // B fragments: attention-MMA1 ldsm4t pattern, n = 4 x 16 cols
            int k = (kt << 4) + l7 + ((g & 1) << 3);
#pragma unroll
            for (int ntp = 0; ntp < 4; ntp++) {
                uint32_t bf4[4];
                int seg = ntp * 2 + (g >> 1);
                ldsm4t(bf4, bb + (k << 7) + ((seg ^ (k & 7)) << 4));
#pragma unroll
                for (int mt = 0; mt < 2; mt++) {
                    mma_hf32(c[mt][ntp * 2],     af[mt], bf4);
                    mma_hf32(c[mt][ntp * 2 + 1], af[mt], bf4 + 2);
                }
            }
        }
    }

    float* Cp = Cm ? (Cm + (size_t)blockIdx.z * sC) : nullptr;
    const float* Rp = res ? (res + (size_t)blockIdx.z * sC) : nullptr;

#pragma unroll
    for (int mt = 0; mt < 2; mt++) {
        int m0 = bm + wm + (mt << 4) + gr;
        float bv0 = bias[m0], bv1 = bias[m0 + 8];
#pragma unroll
        for (int nf = 0; nf < 8; nf++) {
            int n = bn + (nf << 3) + (gc << 1);
            float v0 = c[mt][nf][0] + bv0, v1 = c[mt][nf][1] + bv0;
            float v2 = c[mt][nf][2] + bv1, v3 = c[mt][nf][3] + bv1;
            if (mode == 0) {
                if (Rp) {
                    float2 r0 = *(const float2*)&Rp[(size_t)m0 * ldc + n];
                    float2 r1 = *(const float2*)&Rp[(size_t)(m0 + 8) * ldc + n];
                    v0 += r0.x; v1 += r0.y; v2 += r1.x; v3 += r1.y;
                }
                *(float2*)&Cp[(size_t)m0 * ldc + n]       = make_float2(v0, v1);
                *(float2*)&Cp[(size_t)(m0 + 8) * ldc + n] = make_float2(v2, v3);
            } else {
                write_pack(mode, blockIdx.z, m0, n, v0, v1, N);
                write_pack(mode, blockIdx.z, m0 + 8, n, v2, v3, N);
            }
        }
    }
}

// ---------------------------------------------------------------------------
// fp16 flash attention (unchanged from round 13, passing): P in registers,
// 6-slot cp.async ring consumed in chunk pairs, mask LDS only for encoder cols.
// ---------------------------------------------------------------------------
#define QS_OFF   0
#define KS_OFF   16384
#define VS_OFF   65536
#define MADD_OFF 114688
#define ATT_SMEM 115200

__device__ __forceinline__ void prefetch_kv(uint32_t sbase,
    const __half* Kg, const __half* Vg, int c, int slot, int tid)
{
#pragma unroll
    for (int j = 0; j < 4; j++) {
        int i = tid + (j << 8);
        int sel = i >> 9, ch = (i >> 3) & 63, seg = i & 7;
        const __half* src = (sel ? Vg : Kg) + ch * LP_ + (c << 6) + (seg << 3);
        uint32_t dst = sbase + (sel ? VS_OFF : KS_OFF) + slot * 8192
                     + (ch << 7) + ((seg ^ (ch & 7)) << 4);
        cp16(dst, src);
    }
}

__global__ __launch_bounds__(256, 2) void attn_hf_kernel(const unsigned int* __restrict__ mask)
{
    extern __shared__ char smc[];
    const uint32_t sbase = smem_u32(smc);
    int tid = threadIdx.x, lane = tid & 31, wid = tid >> 5;
    int gr = lane >> 2, gc = lane & 3, l7 = lane & 7, g = lane >> 3;
    int bh = blockIdx.y, h = bh & 7;
    int t0 = blockIdx.x << 7;
    int r0w = wid << 4;

    const __half* Qg = g_qp + (size_t)bh * 64 * T_;
    const __half* Kg = g_kp + (size_t)bh * 64 * LP_;
    const __half* Vg = g_vp + (size_t)bh * 64 * LP_;

    float* madd = (float*)(smc + MADD_OFF);
    for (int s = tid; s < 128; s += 256) {
        int col = 1024 + s;
        madd[s] = (col < L_) ? (mask[h * S_ + s] ? 0.f : -10000.f) : -1e30f;
    }

    for (int i = tid; i < 1024; i += 256) {
        int ch = i >> 4, seg = i & 15;
        uint4 v = *(const uint4*)(Qg + ch * T_ + t0 + seg * 8);
        *(uint4*)(smc + QS_OFF + ch * 256 + ((seg ^ (ch & 7)) << 4)) = v;
    }
    __syncthreads();

    uint32_t qf[4][4];
#pragma unroll
    for (int kt = 0; kt < 4; kt++) {
        int ch = kt * 16 + l7 + ((g >> 1) << 3);
        int tb = (r0w << 1) + ((g & 1) << 4);
        ldsm4t(qf[kt], sbase + QS_OFF + ch * 256 + (tb ^ ((ch & 7) << 4)));
    }

    float o[8][4];
#pragma unroll
    for (int nt = 0; nt < 8; nt++)
#pragma unroll
        for (int l = 0; l < 4; l++) o[nt][l] = 0.f;
    float lsum0 = 0.f, lsum1 = 0.f;

    auto process = [&](int c, uint32_t kb, uint32_t vb) {
        float s8[8][4];
#pragma unroll
        for (int nt = 0; nt < 8; nt++)
#pragma unroll
            for (int l = 0; l < 4; l++) s8[nt][l] = 0.f;
#pragma unroll
        for (int kt = 0; kt < 4; kt++) {
            int ch = kt * 16 + l7 + ((g & 1) << 3);
#pragma unroll
            for (int ntp = 0; ntp < 4; ntp++) {
                uint32_t bf4[4];
                int seg = ntp * 2 + (g >> 1);
                ldsm4t(bf4, kb + (ch << 7) + ((seg ^ (ch & 7)) << 4));
                mma_hf32(s8[ntp * 2],     qf[kt], bf4);
                mma_hf32(s8[ntp * 2 + 1], qf[kt], bf4 + 2);
            }
        }
        if (c < 16) {
#pragma unroll
            for (int nt = 0; nt < 8; nt++) {
                float p0 = __expf(s8[nt][0]), p1 = __expf(s8[nt][1]);
                float p2 = __expf(s8[nt][2]), p3 = __expf(s8[nt][3]);
                lsum0 += p0 + p1; lsum1 += p2 + p3;
                s8[nt][0] = p0; s8[nt][1] = p1; s8[nt][2] = p2; s8[nt][3] = p3;
            }
        } else {
            int colb = ((c - 16) << 6);
#pragma unroll
            for (int nt = 0; nt < 8; nt++) {
                int col = colb + nt * 8 + gc * 2;
                float m0 = madd[col], m1 = madd[col + 1];
                float p0 = __expf(s8[nt][0] + m0), p1 = __expf(s8[nt][1] + m1);
                float p2 = __expf(s8[nt][2] + m0), p3 = __expf(s8[nt][3] + m1);
                lsum0 += p0 + p1; lsum1 += p2 + p3;
                s8[nt][0] = p0; s8[nt][1] = p1; s8[nt][2] = p2; s8[nt][3] = p3;
            }
        }
#pragma unroll
        for (int kt = 0; kt < 4; kt++) {
            uint32_t af[4];
            af[0] = pku(s8[2 * kt][0],     s8[2 * kt][1]);
            af[1] = pku(s8[2 * kt][2],     s8[2 * kt][3]);
            af[2] = pku(s8[2 * kt + 1][0], s8[2 * kt + 1][1]);
            af[3] = pku(s8[2 * kt + 1][2], s8[2 * kt + 1][3]);
#pragma unroll
            for (int ntp = 0; ntp < 4; ntp++) {
                uint32_t bv4[4];
                int ch = (ntp * 2 + (g >> 1)) * 8 + l7;
                int sseg = kt * 2 + (g & 1);
                ldsm4(bv4, vb + (ch << 7) + ((sseg ^ (ch & 7)) << 4));
                mma_hf32(o[ntp * 2],     af, bv4);
                mma_hf32(o[ntp * 2 + 1], af, bv4 + 2);
            }
        }
    };

    prefetch_kv(sbase, Kg, Vg, 0, 0, tid); CP_COMMIT();
    prefetch_kv(sbase, Kg, Vg, 1, 1, tid); CP_COMMIT();
    prefetch_kv(sbase, Kg, Vg, 2, 2, tid); CP_COMMIT();
    prefetch_kv(sbase, Kg, Vg, 3, 3, tid); CP_COMMIT();

    for (int it = 0; it < 9; it++) {
        int c0 = it << 1;
        CP_WAIT2();
        __syncthreads();
        if (c0 + 4 < 18) prefetch_kv(sbase, Kg, Vg, c0 + 4, (c0 + 4) % 6, tid);
        CP_COMMIT();
        if (c0 + 5 < 18) prefetch_kv(sbase, Kg, Vg, c0 + 5, (c0 + 5) % 6, tid);
        CP_COMMIT();
        int s0 = c0 % 6, s1 = (c0 + 1) % 6;
        process(c0,     sbase + KS_OFF + s0 * 8192, sbase + VS_OFF + s0 * 8192);
        process(c0 + 1, sbase + KS_OFF + s1 * 8192, sbase + VS_OFF + s1 * 8192);
    }

    lsum0 += __shfl_xor_sync(0xffffffffu, lsum0, 1);
    lsum0 += __shfl_xor_sync(0xffffffffu, lsum0, 2);
    lsum1 += __shfl_xor_sync(0xffffffffu, lsum1, 1);
    lsum1 += __shfl_xor_sync(0xffffffffu, lsum1, 2);
    float inv0 = 1.f / lsum0, inv1 = 1.f / lsum1;

    __syncthreads();
    float* tr = (float*)smc;   // [64][132] floats
    int r0g = r0w + gr;
#pragma unroll
    for (int nt = 0; nt < 8; nt++) {
        int ch = nt * 8 + gc * 2;
        tr[ch * 132 + r0g]           = o[nt][0] * inv0;
        tr[(ch + 1) * 132 + r0g]     = o[nt][1] * inv0;
        tr[ch * 132 + r0g + 8]       = o[nt][2] * inv1;
        tr[(ch + 1) * 132 + r0g + 8] = o[nt][3] * inv1;
    }
    __syncthreads();
    __half* ob = g_attb + ((size_t)(bh >> 3) * C_ + h * CH_) * T_ + t0;
    for (int i = tid; i < 8192; i += 256) {
        int ch = i >> 7, t = i & 127;
        ob[(size_t)ch * T_ + t] = __float2half_rn(tr[ch * 132 + t]);
    }
}

// ---------------------------------------------------------------------------
extern "C" void kernel_launch(void* const* d_in, const int* in_sizes, int n_in,
                              void* d_out, int out_size)
{
    (void)in_sizes; (void)n_in; (void)out_size;
    const float* x       = (const float*)d_in[0];
    const float* enc     = (const float*)d_in[1];
    const unsigned int* mask = (const unsigned int*)d_in[2];
    const float* gamma   = (const float*)d_in[3];
    const float* beta    = (const float*)d_in[4];
    const float* qkv_w   = (const float*)d_in[5];
    const float* qkv_b   = (const float*)d_in[6];
    const float* ekv_w   = (const float*)d_in[7];
    const float* ekv_b   = (const float*)d_in[8];
    const float* proj_w  = (const float*)d_in[9];
    const float* proj_b  = (const float*)d_in[10];
    float* out = (float*)d_out;

    __half *qkvwb, *ekvwb, *projwb, *encb, *nrmb, *attb;
    cudaGetSymbolAddress((void**)&qkvwb, g_qkvwb);
    cudaGetSymbolAddress((void**)&ekvwb, g_ekvwb);
    cudaGetSymbolAddress((void**)&projwb, g_projwb);
    cudaGetSymbolAddress((void**)&encb, g_encb);
    cudaGetSymbolAddress((void**)&nrmb, g_nrmb);
    cudaGetSymbolAddress((void**)&attb, g_attb);

    cudaFuncSetAttribute(gemm_hf, cudaFuncAttributeMaxDynamicSharedMemorySize, GEMM_SMEM);
    cudaFuncSetAttribute(attn_hf_kernel, cudaFuncAttributeMaxDynamicSharedMemorySize, ATT_SMEM);

    // 1. fused weight/encoder conversion + GroupNorm
    prep_kernel<<<NCONVB + B_ * GROUPS_, 256>>>(x, gamma, beta, qkv_w, ekv_w, proj_w, enc);

    // 2. fused qkv (12 y-rows x 16 n-tiles of 64) + ekv (1 extra y row = 16 blocks)
    gemm_hf<<<dim3(16, 13, B_), 128, GEMM_SMEM>>>(qkvwb, nrmb, qkv_b, nullptr, nullptr,
        1024, 512, T_, (long long)C_ * T_, 0, 0, 1, 12,
        ekvwb, encb, ekv_b, S_, 256, (long long)512 * 256, 2);

    // 3. fp16 flash attention
    attn_hf_kernel<<<dim3(8, 64), 256, ATT_SMEM>>>(mask);

    // 4. output projection + bias + residual -> d_out
    gemm_hf<<<dim3(16, 4, B_), 128, GEMM_SMEM>>>(projwb, attb, proj_b, x, out,
        1024, 512, T_, (long long)C_ * T_, T_, (long long)C_ * T_, 0, 4,
        nullptr, nullptr, nullptr, 0, 0, 0, 0);
}

// round 15
// speedup vs baseline: 1.2362x; 1.0468x over previous
#include <cuda_runtime.h>
#include <cuda_fp16.h>
#include <cstdint>

#define B_      8
#define C_      512
#define T_      1024
#define HEADS_  8
#define CH_     64
#define S_      77
#define L_      1101
#define LP_     1152
#define GROUPS_ 32
#define CPG_    16
#define LOG2E   1.44269504088896f

// Scratch (static device globals) — all 16-bit tensors are fp16
static __device__ __half g_nrmb[B_ * C_ * T_];
static __device__ __half g_attb[B_ * C_ * T_];
static __device__ __half g_qp[B_ * HEADS_ * CH_ * T_];   // [bh][ch][t], pre-scaled 1/8*log2e
static __device__ __half g_kp[B_ * HEADS_ * CH_ * LP_];  // [bh][ch][self|enc|pad]
static __device__ __half g_vp[B_ * HEADS_ * CH_ * LP_];
static __device__ __half g_qkvwb[1536 * 512];
static __device__ __half g_ekvwb[1024 * 512];
static __device__ __half g_projwb[512 * 512];
static __device__ __half g_encb[B_ * 512 * 256];         // padded 77->256, zero-filled

// ---------------------------------------------------------------------------
// PTX helpers
// ---------------------------------------------------------------------------
__device__ __forceinline__ uint32_t smem_u32(const void* p) {
    uint32_t a;
    asm("{ .reg .u64 t; cvta.to.shared.u64 t, %1; cvt.u32.u64 %0, t; }" : "=r"(a) : "l"(p));
    return a;
}
__device__ __forceinline__ void mma_hf32(float* c, const uint32_t* a, const uint32_t* b) {
    asm volatile("mma.sync.aligned.m16n8k16.row.col.f32.f16.f16.f32 "
        "{%0,%1,%2,%3}, {%4,%5,%6,%7}, {%8,%9}, {%0,%1,%2,%3};"
        : "+f"(c[0]), "+f"(c[1]), "+f"(c[2]), "+f"(c[3])
        : "r"(a[0]), "r"(a[1]), "r"(a[2]), "r"(a[3]), "r"(b[0]), "r"(b[1]));
}
__device__ __forceinline__ void ldsm4(uint32_t* r, uint32_t a) {
    asm volatile("ldmatrix.sync.aligned.m8n8.x4.shared.b16 {%0,%1,%2,%3}, [%4];"
        : "=r"(r[0]), "=r"(r[1]), "=r"(r[2]), "=r"(r[3]) : "r"(a));
}
__device__ __forceinline__ void ldsm4t(uint32_t* r, uint32_t a) {
    asm volatile("ldmatrix.sync.aligned.m8n8.x4.trans.shared.b16 {%0,%1,%2,%3}, [%4];"
        : "=r"(r[0]), "=r"(r[1]), "=r"(r[2]), "=r"(r[3]) : "r"(a));
}
__device__ __forceinline__ void cp16(uint32_t dst, const void* src) {
    asm volatile("cp.async.cg.shared.global [%0], [%1], 16;" :: "r"(dst), "l"(src));
}
#define CP_COMMIT() asm volatile("cp.async.commit_group;" ::: "memory")
#define CP_WAIT2()  asm volatile("cp.async.wait_group 2;" ::: "memory")

__device__ __forceinline__ __half2 pack2h(float a, float b) {
    return __floats2half2_rn(a, b);
}
__device__ __forceinline__ uint32_t pku(float lo, float hi) {
    __half2 t = __floats2half2_rn(lo, hi);
    return *reinterpret_cast<uint32_t*>(&t);
}
__device__ __forceinline__ uint32_t ex2h2(uint32_t x) {
    uint32_t r;
    asm("ex2.approx.f16x2 %0, %1;" : "=r"(r) : "r"(x));
    return r;
}
__device__ __forceinline__ uint32_t hadd2u(uint32_t a, uint32_t b) {
    uint32_t r;
    asm("add.f16x2 %0, %1, %2;" : "=r"(r) : "r"(a), "r"(b));
    return r;
}

// ---------------------------------------------------------------------------
// Fused prep (vectorized): weight/encoder fp16 conversion + GroupNorm32
// ---------------------------------------------------------------------------
#define NQW 786432
#define NEW 524288
#define NPW 262144
#define NEN 1048576
#define NCV 1536          // (NQW+NEW+NPW)/1024 float4-blocks
#define NEB 4096          // NEN/256 scalar blocks
#define PREP_GRID (NCV + NEB + B_ * GROUPS_)

__global__ __launch_bounds__(256) void prep_kernel(
    const float* __restrict__ x, const float* __restrict__ gamma,
    const float* __restrict__ beta,
    const float* __restrict__ qkvw, const float* __restrict__ ekvw,
    const float* __restrict__ projw, const float* __restrict__ enc)
{
    if (blockIdx.x < NCV) {
        int base = (blockIdx.x * 256 + threadIdx.x) * 4;
        const float* src;
        __half* dst;
        if (base < NQW)            { src = qkvw + base; dst = g_qkvwb + base; }
        else if (base < NQW + NEW) { src = ekvw + base - NQW; dst = g_ekvwb + base - NQW; }
        else                       { src = projw + base - NQW - NEW; dst = g_projwb + base - NQW - NEW; }
        float4 v = *(const float4*)src;
        uint2 o;
        o.x = pku(v.x, v.y); o.y = pku(v.z, v.w);
        *(uint2*)dst = o;
        return;
    }
    if (blockIdx.x < NCV + NEB) {
        int e = (blockIdx.x - NCV) * 256 + threadIdx.x;
        int t = e & 255, row = e >> 8;
        g_encb[e] = (t < S_) ? __float2half_rn(enc[row * S_ + t]) : __half(0.f);
        return;
    }
    int bg = blockIdx.x - NCV - NEB;
    int b = bg / GROUPS_, g = bg % GROUPS_;
    const float4* xp4 = (const float4*)(x + ((size_t)b * C_ + g * CPG_) * T_);
    __half* op = g_nrmb + ((size_t)b * C_ + g * CPG_) * T_;
    const int N4 = CPG_ * T_ / 4;   // 4096

    float s = 0.f, q = 0.f;
    for (int i = threadIdx.x; i < N4; i += 256) {
        float4 v = xp4[i];
        s += v.x + v.y + v.z + v.w;
        q = fmaf(v.x, v.x, q); q = fmaf(v.y, v.y, q);
        q = fmaf(v.z, v.z, q); q = fmaf(v.w, v.w, q);
    }
    __shared__ float rs[256], rq[256];
    rs[threadIdx.x] = s; rq[threadIdx.x] = q;
    __syncthreads();
    for (int o = 128; o > 0; o >>= 1) {
        if (threadIdx.x < o) { rs[threadIdx.x] += rs[threadIdx.x + o]; rq[threadIdx.x] += rq[threadIdx.x + o]; }
        __syncthreads();
    }
    const float Nf = (float)(CPG_ * T_);
    float mean = rs[0] / Nf;
    float var  = rq[0] / Nf - mean * mean;
    float inv  = rsqrtf(var + 1e-5f);
    for (int i = threadIdx.x; i < N4; i += 256) {
        int c = g * CPG_ + (i >> 8);
        float sc = inv * gamma[c], sh = beta[c] - mean * sc;
        float4 v = xp4[i];
        uint2 o;
        o.x = pku(fmaf(v.x, sc, sh), fmaf(v.y, sc, sh));
        o.y = pku(fmaf(v.z, sc, sh), fmaf(v.w, sc, sh));
        *(uint2*)&op[i * 4] = o;
    }
}

// ---------------------------------------------------------------------------
// Epilogue pack writer (head-major row decode); q pre-scaled by log2e/8
// ---------------------------------------------------------------------------
__device__ __forceinline__ void write_pack(int mode, int z, int m, int n, float v0, float v1, int N) {
    int h, type, ch;
    if (mode == 1) {
        h = m / 192;
        int sub = m - h * 192;
        type = sub >> 6; ch = sub & 63;
    } else {
        h = m >> 7;
        type = (m >> 6) & 1; ch = m & 63;
    }
    size_t row = (size_t)(z * 8 + h) * 64 + ch;
    if (mode == 1) {
        if (type == 0) {
            const float qs = 0.125f * LOG2E;
            *(__half2*)&g_qp[row * T_ + n] = pack2h(v0 * qs, v1 * qs);
        } else {
            __half* p = (type == 1 ? g_kp : g_vp) + row * LP_ + n;
            *(__half2*)p = pack2h(v0, v1);
        }
    } else {
        __half* p = (type == 0 ? g_kp : g_vp) + row * LP_ + 1024 + n;
        if (n + 1 < N)      *(__half2*)p = pack2h(v0, v1);
        else if (n < N)     *p = __float2half_rn(v0);
    }
}

// ---------------------------------------------------------------------------
// fp16 mma.sync GEMM v4 (unchanged from round 14, passing): CTA 128x64,
// 128 threads / 4 warps (each 32Mx64N), f32 accums, 4-slot cp.async ring.
// ---------------------------------------------------------------------------
#define GEMM_SMEM 49152

__global__ __launch_bounds__(128, 4) void gemm_hf(
    const __half* __restrict__ A, const __half* __restrict__ Bm,
    const float* __restrict__ bias, const float* __restrict__ res,
    float* __restrict__ Cm, int N, int K, int ldb, long long sB,
    int ldc, long long sC, int mode, int ytiles,
    const __half* __restrict__ A2, const __half* __restrict__ B2,
    const float* __restrict__ bias2, int N2, int ldb2, long long sB2, int mode2)
{
    extern __shared__ __half dsm[];
    const uint32_t sa = smem_u32(dsm), sb = sa + 32768;

    int bm, bn;
    if (A2 && (int)blockIdx.y >= ytiles) {
        A = A2; Bm = B2; bias = bias2; N = N2; ldb = ldb2; sB = sB2; mode = mode2;
        bm = ((int)blockIdx.x >> 1) << 7;
        bn = ((int)blockIdx.x & 1) << 6;
    } else {
        bm = blockIdx.y << 7; bn = blockIdx.x << 6;
    }

    int tid = threadIdx.x, wid = tid >> 5, lane = tid & 31;
    int wm = wid << 5;
    int gr = lane >> 2, gc = lane & 3;
    int l7 = lane & 7, g = lane >> 3;

    const __half* Ab = A + (size_t)bm * K;
    const __half* Bb = Bm + (size_t)blockIdx.z * sB + bn;

    int a_m  = l7 + ((g & 1) << 3);
    int a_kc = lane >> 4;

    float c[2][8][4];
#pragma unroll
    for (int i = 0; i < 2; i++)
#pragma unroll
        for (int j = 0; j < 8; j++)
#pragma unroll
            for (int l = 0; l < 4; l++) c[i][j][l] = 0.f;

    auto load_tiles = [&](int k0, int slot) {
#pragma unroll
        for (int j = 0; j < 4; j++) {
            int idx = tid + (j << 7);
            int m = idx >> 2, kc = idx & 3;
            cp16(sa + slot * 8192 + m * 64 + ((kc ^ ((m >> 1) & 3)) << 4),
                 Ab + (size_t)m * K + k0 + kc * 8);
        }
#pragma unroll
        for (int j = 0; j < 2; j++) {
            int idx = tid + (j << 7);
            int k = idx >> 3, seg = idx & 7;
            cp16(sb + slot * 4096 + k * 128 + ((seg ^ (k & 7)) << 4),
                 Bb + (size_t)(k0 + k) * ldb + seg * 8);
        }
    };

    int nsteps = K >> 5;
    load_tiles(0, 0); CP_COMMIT();
    load_tiles(32, 1); CP_COMMIT();
    load_tiles(64, 2); CP_COMMIT();

    for (int s = 0; s < nsteps; s++) {
        CP_WAIT2();
        __syncthreads();
        if (s + 3 < nsteps) load_tiles((s + 3) << 5, (s + 3) & 3);
        CP_COMMIT();
        uint32_t ab = sa + (s & 3) * 8192, bb = sb + (s & 3) * 4096;

#pragma unroll
        for (int kt = 0; kt < 2; kt++) {
            uint32_t af[2][4];
            int kc = (kt << 1) + a_kc;
#pragma unroll
            for (int mt = 0; mt < 2; mt++) {
                int m = wm + (mt << 4) + a_m;
                ldsm4(af[mt], ab + m * 64 + ((kc ^ ((m >> 1) & 3)) << 4));
            }
            int k = (kt << 4) + l7 + ((g & 1) << 3);
#pragma unroll
            for (int ntp = 0; ntp < 4; ntp++) {
                uint32_t bf4[4];
                int seg = ntp * 2 + (g >> 1);
                ldsm4t(bf4, bb + (k << 7) + ((seg ^ (k & 7)) << 4));
#pragma unroll
                for (int mt = 0; mt < 2; mt++) {
                    mma_hf32(c[mt][ntp * 2],     af[mt], bf4);
                    mma_hf32(c[mt][ntp * 2 + 1], af[mt], bf4 + 2);
                }
            }
        }
    }

    float* Cp = Cm ? (Cm + (size_t)blockIdx.z * sC) : nullptr;
    const float* Rp = res ? (res + (size_t)blockIdx.z * sC) : nullptr;

#pragma unroll
    for (int mt = 0; mt < 2; mt++) {
        int m0 = bm + wm + (mt << 4) + gr;
        float bv0 = bias[m0], bv1 = bias[m0 + 8];
#pragma unroll
        for (int nf = 0; nf < 8; nf++) {
            int n = bn + (nf << 3) + (gc << 1);
            float v0 = c[mt][nf][0] + bv0, v1 = c[mt][nf][1] + bv0;
            float v2 = c[mt][nf][2] + bv1, v3 = c[mt][nf][3] + bv1;
            if (mode == 0) {
                if (Rp) {
                    float2 r0 = *(const float2*)&Rp[(size_t)m0 * ldc + n];
                    float2 r1 = *(const float2*)&Rp[(size_t)(m0 + 8) * ldc + n];
                    v0 += r0.x; v1 += r0.y; v2 += r1.x; v3 += r1.y;
                }
                *(float2*)&Cp[(size_t)m0 * ldc + n]       = make_float2(v0, v1);
                *(float2*)&Cp[(size_t)(m0 + 8) * ldc + n] = make_float2(v2, v3);
            } else {
                write_pack(mode, blockIdx.z, m0, n, v0, v1, N);
                write_pack(mode, blockIdx.z, m0 + 8, n, v2, v3, N);
            }
        }
    }
}

// ---------------------------------------------------------------------------
// fp16 flash attention, log2-domain softmax via ex2.approx.f16x2.
// Scores from MMA1 are already log2-scaled (q pre-scaled by log2e/8; mask
// table pre-scaled by log2e). P fragments = ex2(pack(s)) directly; row sums
// accumulated in f16x2, converted to f32 once per chunk.
// ---------------------------------------------------------------------------
#define QS_OFF   0
#define KS_OFF   16384
#define VS_OFF   65536
#define MADD_OFF 114688
#define ATT_SMEM 115200

__device__ __forceinline__ void prefetch_kv(uint32_t sbase,
    const __half* Kg, const __half* Vg, int c, int slot, int tid)
{
#pragma unroll
    for (int j = 0; j < 4; j++) {
        int i = tid + (j << 8);
        int sel = i >> 9, ch = (i >> 3) & 63, seg = i & 7;
        const __half* src = (sel ? Vg : Kg) + ch * LP_ + (c << 6) + (seg << 3);
        uint32_t dst = sbase + (sel ? VS_OFF : KS_OFF) + slot * 8192
                     + (ch << 7) + ((seg ^ (ch & 7)) << 4);
        cp16(dst, src);
    }
}

__global__ __launch_bounds__(256, 2) void attn_hf_kernel(const unsigned int* __restrict__ mask)
{
    extern __shared__ char smc[];
    const uint32_t sbase = smem_u32(smc);
    int tid = threadIdx.x, lane = tid & 31, wid = tid >> 5;
    int gr = lane >> 2, gc = lane & 3, l7 = lane & 7, g = lane >> 3;
    int bh = blockIdx.y, h = bh & 7;
    int t0 = blockIdx.x << 7;
    int r0w = wid << 4;

    const __half* Qg = g_qp + (size_t)bh * 64 * T_;
    const __half* Kg = g_kp + (size_t)bh * 64 * LP_;
    const __half* Vg = g_vp + (size_t)bh * 64 * LP_;

    float* madd = (float*)(smc + MADD_OFF);
    for (int s = tid; s < 128; s += 256) {
        int col = 1024 + s;
        madd[s] = (col < L_) ? (mask[h * S_ + s] ? 0.f : -10000.f * LOG2E) : -1e30f;
    }

    for (int i = tid; i < 1024; i += 256) {
        int ch = i >> 4, seg = i & 15;
        uint4 v = *(const uint4*)(Qg + ch * T_ + t0 + seg * 8);
        *(uint4*)(smc + QS_OFF + ch * 256 + ((seg ^ (ch & 7)) << 4)) = v;
    }
    __syncthreads();

    uint32_t qf[4][4];
#pragma unroll
    for (int kt = 0; kt < 4; kt++) {
        int ch = kt * 16 + l7 + ((g >> 1) << 3);
        int tb = (r0w << 1) + ((g & 1) << 4);
        ldsm4t(qf[kt], sbase + QS_OFF + ch * 256 + (tb ^ ((ch & 7) << 4)));
    }

    float o[8][4];
#pragma unroll
    for (int nt = 0; nt < 8; nt++)
#pragma unroll
        for (int l = 0; l < 4; l++) o[nt][l] = 0.f;
    float lsum0 = 0.f, lsum1 = 0.f;

    auto process = [&](int c, uint32_t kb, uint32_t vb) {
        float s8[8][4];
#pragma unroll
        for (int nt = 0; nt < 8; nt++)
#pragma unroll
            for (int l = 0; l < 4; l++) s8[nt][l] = 0.f;
#pragma unroll
        for (int kt = 0; kt < 4; kt++) {
            int ch = kt * 16 + l7 + ((g & 1) << 3);
#pragma unroll
            for (int ntp = 0; ntp < 4; ntp++) {
                uint32_t bf4[4];
                int seg = ntp * 2 + (g >> 1);
                ldsm4t(bf4, kb + (ch << 7) + ((seg ^ (ch & 7)) << 4));
                mma_hf32(s8[ntp * 2],     qf[kt], bf4);
                mma_hf32(s8[ntp * 2 + 1], qf[kt], bf4 + 2);
            }
        }
        // encoder chunks: add log2-scaled additive mask; self chunks need nothing
        if (c >= 16) {
            int colb = ((c - 16) << 6);
#pragma unroll
            for (int nt = 0; nt < 8; nt++) {
                int col = colb + nt * 8 + gc * 2;
                float m0 = madd[col], m1 = madd[col + 1];
                s8[nt][0] += m0; s8[nt][1] += m1;
                s8[nt][2] += m0; s8[nt][3] += m1;
            }
        }
        // MMA2: P = 2^s computed straight into A-fragments; f16x2 row sums
        uint32_t hs0 = 0u, hs1 = 0u;
#pragma unroll
        for (int kt = 0; kt < 4; kt++) {
            uint32_t af[4];
            af[0] = ex2h2(pku(s8[2 * kt][0],     s8[2 * kt][1]));
            af[1] = ex2h2(pku(s8[2 * kt][2],     s8[2 * kt][3]));
            af[2] = ex2h2(pku(s8[2 * kt + 1][0], s8[2 * kt + 1][1]));
            af[3] = ex2h2(pku(s8[2 * kt + 1][2], s8[2 * kt + 1][3]));
            hs0 = hadd2u(hs0, hadd2u(af[0], af[2]));
            hs1 = hadd2u(hs1, hadd2u(af[1], af[3]));
#pragma unroll
            for (int ntp = 0; ntp < 4; ntp++) {
                uint32_t bv4[4];
                int ch = (ntp * 2 + (g >> 1)) * 8 + l7;
                int sseg = kt * 2 + (g & 1);
                ldsm4(bv4, vb + (ch << 7) + ((sseg ^ (ch & 7)) << 4));
                mma_hf32(o[ntp * 2],     af, bv4);
                mma_hf32(o[ntp * 2 + 1], af, bv4 + 2);
            }
        }
        __half2 h0 = *(__half2*)&hs0, h1 = *(__half2*)&hs1;
        lsum0 += __half2float(h0.x) + __half2float(h0.y);
        lsum1 += __half2float(h1.x) + __half2float(h1.y);
    };

    prefetch_kv(sbase, Kg, Vg, 0, 0, tid); CP_COMMIT();
    prefetch_kv(sbase, Kg, Vg, 1, 1, tid); CP_COMMIT();
    prefetch_kv(sbase, Kg, Vg, 2, 2, tid); CP_COMMIT();
    prefetch_kv(sbase, Kg, Vg, 3, 3, tid); CP_COMMIT();

    for (int it = 0; it < 9; it++) {
        int c0 = it << 1;
        CP_WAIT2();
        __syncthreads();
        if (c0 + 4 < 18) prefetch_kv(sbase, Kg, Vg, c0 + 4, (c0 + 4) % 6, tid);
        CP_COMMIT();
        if (c0 + 5 < 18) prefetch_kv(sbase, Kg, Vg, c0 + 5, (c0 + 5) % 6, tid);
        CP_COMMIT();
        int s0 = c0 % 6, s1 = (c0 + 1) % 6;
        process(c0,     sbase + KS_OFF + s0 * 8192, sbase + VS_OFF + s0 * 8192);
        process(c0 + 1, sbase + KS_OFF + s1 * 8192, sbase + VS_OFF + s1 * 8192);
    }

    lsum0 += __shfl_xor_sync(0xffffffffu, lsum0, 1);
    lsum0 += __shfl_xor_sync(0xffffffffu, lsum0, 2);
    lsum1 += __shfl_xor_sync(0xffffffffu, lsum1, 1);
    lsum1 += __shfl_xor_sync(0xffffffffu, lsum1, 2);
    float inv0 = 1.f / lsum0, inv1 = 1.f / lsum1;

    __syncthreads();
    float* tr = (float*)smc;   // [64][132] floats
    int r0g = r0w + gr;
#pragma unroll
    for (int nt = 0; nt < 8; nt++) {
        int ch = nt * 8 + gc * 2;
        tr[ch * 132 + r0g]           = o[nt][0] * inv0;
        tr[(ch + 1) * 132 + r0g]     = o[nt][1] * inv0;
        tr[ch * 132 + r0g + 8]       = o[nt][2] * inv1;
        tr[(ch + 1) * 132 + r0g + 8] = o[nt][3] * inv1;
    }
    __syncthreads();
    __half* ob = g_attb + ((size_t)(bh >> 3) * C_ + h * CH_) * T_ + t0;
    for (int i = tid; i < 8192; i += 256) {
        int ch = i >> 7, t = i & 127;
        ob[(size_t)ch * T_ + t] = __float2half_rn(tr[ch * 132 + t]);
    }
}

// ---------------------------------------------------------------------------
extern "C" void kernel_launch(void* const* d_in, const int* in_sizes, int n_in,
                              void* d_out, int out_size)
{
    (void)in_sizes; (void)n_in; (void)out_size;
    const float* x       = (const float*)d_in[0];
    const float* enc     = (const float*)d_in[1];
    const unsigned int* mask = (const unsigned int*)d_in[2];
    const float* gamma   = (const float*)d_in[3];
    const float* beta    = (const float*)d_in[4];
    const float* qkv_w   = (const float*)d_in[5];
    const float* qkv_b   = (const float*)d_in[6];
    const float* ekv_w   = (const float*)d_in[7];
    const float* ekv_b   = (const float*)d_in[8];
    const float* proj_w  = (const float*)d_in[9];
    const float* proj_b  = (const float*)d_in[10];
    float* out = (float*)d_out;

    __half *qkvwb, *ekvwb, *projwb, *encb, *nrmb, *attb;
    cudaGetSymbolAddress((void**)&qkvwb, g_qkvwb);
    cudaGetSymbolAddress((void**)&ekvwb, g_ekvwb);
    cudaGetSymbolAddress((void**)&projwb, g_projwb);
    cudaGetSymbolAddress((void**)&encb, g_encb);
    cudaGetSymbolAddress((void**)&nrmb, g_nrmb);
    cudaGetSymbolAddress((void**)&attb, g_attb);

    cudaFuncSetAttribute(gemm_hf, cudaFuncAttributeMaxDynamicSharedMemorySize, GEMM_SMEM);
    cudaFuncSetAttribute(attn_hf_kernel, cudaFuncAttributeMaxDynamicSharedMemorySize, ATT_SMEM);

    // 1. fused weight/encoder conversion + GroupNorm (vectorized)
    prep_kernel<<<PREP_GRID, 256>>>(x, gamma, beta, qkv_w, ekv_w, proj_w, enc);

    // 2. fused qkv (12 y-rows x 16 n-tiles of 64) + ekv (1 extra y row)
    gemm_hf<<<dim3(16, 13, B_), 128, GEMM_SMEM>>>(qkvwb, nrmb, qkv_b, nullptr, nullptr,
        1024, 512, T_, (long long)C_ * T_, 0, 0, 1, 12,
        ekvwb, encb, ekv_b, S_, 256, (long long)512 * 256, 2);

    // 3. fp16 flash attention (log2-domain softmax)
    attn_hf_kernel<<<dim3(8, 64), 256, ATT_SMEM>>>(mask);

    // 4. output projection + bias + residual -> d_out
    gemm_hf<<<dim3(16, 4, B_), 128, GEMM_SMEM>>>(projwb, attb, proj_b, x, out,
        1024, 512, T_, (long long)C_ * T_, T_, (long long)C_ * T_, 0, 4,
        nullptr, nullptr, nullptr, 0, 0, 0, 0);
}